// round 15
// baseline (speedup 1.0000x reference)
#include <cuda_runtime.h>
#include <cuda_fp16.h>
#include <cstdint>

// ---------------------------------------------------------------------------
// Output tuple layout (flattened, reference return order)
// ---------------------------------------------------------------------------
static const size_t OFF_QUANT = 1;         // [32,128,32,32]
static const size_t OFF_PERP  = 4194305;   // scalar
static const size_t OFF_ENC   = 4194306;   // [32768,1024]
static const size_t OFF_TOPK  = 37748738;  // [3,32,32,32,128]

__device__ float g_loss_sum;   // zero-init; reset by last CTA each launch
__device__ int   g_counts[1024];
__device__ int   g_done;

// ---------------------------------------------------------------------------
// helpers
// ---------------------------------------------------------------------------
__device__ __forceinline__ uint32_t smem_u32(const void* p) {
    uint32_t a;
    asm("{ .reg .u64 t; cvta.to.shared.u64 t, %1; cvt.u32.u64 %0, t; }" : "=r"(a) : "l"(p));
    return a;
}

__device__ __forceinline__ void ldsm4(uint32_t r[4], uint32_t addr) {
    asm volatile("ldmatrix.sync.aligned.m8n8.x4.shared.b16 {%0,%1,%2,%3}, [%4];"
                 : "=r"(r[0]), "=r"(r[1]), "=r"(r[2]), "=r"(r[3]) : "r"(addr));
}
// f16 MMA with f16 accumulators (2 regs)
__device__ __forceinline__ void mma16816h(uint32_t& c0, uint32_t& c1,
                                          const uint32_t a[4], uint32_t b0, uint32_t b1) {
    asm volatile("mma.sync.aligned.m16n8k16.row.col.f16.f16.f16.f16 "
                 "{%0,%1},{%2,%3,%4,%5},{%6,%7},{%0,%1};"
                 : "+r"(c0), "+r"(c1)
                 : "r"(a[0]), "r"(a[1]), "r"(a[2]), "r"(a[3]), "r"(b0), "r"(b1));
}

// monotone float->u32, key ROUNDED to 22 bits + 10-bit embedding index
__device__ __forceinline__ uint32_t mpack(float k, int e) {
    uint32_t u = __float_as_uint(k);
    u ^= (uint32_t)((int)u >> 31) | 0x80000000u;
    return ((u + 0x200u) & 0xFFFFFC00u) | (uint32_t)e;
}
// branchless sorted-4 insert (7 IMNMX)
__device__ __forceinline__ void ins4u(uint32_t x, uint32_t& v0, uint32_t& v1,
                                      uint32_t& v2, uint32_t& v3) {
    uint32_t t;
    t = min(v0, x); x = max(v0, x); v0 = t;
    t = min(v1, x); x = max(v1, x); v1 = t;
    t = min(v2, x); x = max(v2, x); v2 = t;
    v3 = min(v3, x);
}

__device__ __forceinline__ unsigned long long packkey(float k, int idx) {
    unsigned u = __float_as_uint(k);
    u = (u & 0x80000000u) ? ~u : (u | 0x80000000u);
    return ((unsigned long long)u << 32) | (unsigned)idx;
}
__device__ __forceinline__ void ins3(unsigned long long pk,
                                     unsigned long long& a0, unsigned long long& a1,
                                     unsigned long long& a2) {
    if (pk < a2) {
        if (pk < a1) { a2 = a1; if (pk < a0) { a1 = a0; a0 = pk; } else a1 = pk; }
        else a2 = pk;
    }
}

// ---------------------------------------------------------------------------
// SMEM layout (bytes).  Pool is a union:
//   main loop : B0 (16KB) | B1 (16KB)   f16 chunk double buffer
//   rescore   : PK u64[128][16] (16KB) | CI int[128][16] (8KB)
//   epilogue  : ES half-tile float[128][68] (34816)
// ---------------------------------------------------------------------------
#define SM_XP     0u        // float [128 p][132 d]  (67584B)
#define SM_POOL   67584u
#define SM_B0     (SM_POOL + 0u)
#define SM_B1     (SM_POOL + 16384u)
#define SM_PK     (SM_POOL + 0u)       // u64 [128][16]
#define SM_CI     (SM_POOL + 16384u)   // int [128][16]
#define SM_ES     (SM_POOL + 0u)       // float [128][68]
#define SM_EN     102400u   // float [1024]  (filled incrementally per chunk)
#define SM_SIDX   106496u   // int [128][3]
#define SMEM_TOTAL 108032u

// ---------------------------------------------------------------------------
// Fill chunk (64 embs) : fp32 emb -> f16 swizzled smem, + fp32 enorm into EN.
// 16 warps: warp covers 4 rows, lane = float4 column.
// ---------------------------------------------------------------------------
__device__ __forceinline__ void fill_chunk(char* smem, float* EN,
                                           const float4* e4, int e0,
                                           uint32_t bufoff, int wid, int lane) {
    #pragma unroll
    for (int i = 0; i < 4; i++) {
        int row = wid * 4 + i;
        float4 v = e4[(size_t)(e0 + row) * 32 + lane];
        float s = fmaf(v.x, v.x, fmaf(v.y, v.y, fmaf(v.z, v.z, v.w * v.w)));
        #pragma unroll
        for (int o = 16; o; o >>= 1) s += __shfl_down_sync(0xffffffffu, s, o);
        if (lane == 0) EN[e0 + row] = s;
        __half2 h0 = __floats2half2_rn(v.x, v.y);
        __half2 h1 = __floats2half2_rn(v.z, v.w);
        uint32_t byte = (uint32_t)(row * 256 + ((((lane >> 1) ^ (row & 7))) << 4) + ((lane & 1) << 3));
        *(uint2*)(smem + bufoff + byte) = make_uint2(*(uint32_t*)&h0, *(uint32_t*)&h1);
    }
}

// ---------------------------------------------------------------------------
__global__ void __launch_bounds__(512, 2) k_all(const float* __restrict__ inp,
                                                const float* __restrict__ emb,
                                                float* __restrict__ out) {
    extern __shared__ char smem[];
    const uint32_t sb = smem_u32(smem);
    float* XP = (float*)(smem + SM_XP);
    float* EN = (float*)(smem + SM_EN);
    int*   CI = (int*)(smem + SM_CI);
    unsigned long long* PK = (unsigned long long*)(smem + SM_PK);
    int*   SIDX = (int*)(smem + SM_SIDX);
    float* ES = (float*)(smem + SM_ES);
    __shared__ int s_last;

    const int t    = threadIdx.x;
    const int lane = t & 31;
    const int wid  = t >> 5;          // 0..15
    const int h    = wid & 1;         // nt half
    const int n0   = blockIdx.x * 128;
    const int b    = n0 >> 10;
    const int hw0  = n0 & 1023;
    const float* inbase = inp + (size_t)b * 131072 + hw0;
    const float4* e4 = (const float4*)emb;

    // ---- prologue: XP fp32, enc zero, chunk0 fill ----
    for (int i = t; i < 128 * 64; i += 512) {
        int d2 = i >> 7, p = i & 127;
        XP[p * 132 + 2 * d2]     = inbase[(size_t)(2 * d2)     * 1024 + p];
        XP[p * 132 + 2 * d2 + 1] = inbase[(size_t)(2 * d2 + 1) * 1024 + p];
    }
    {   // zero 128 encoding rows: 8B head, 32766 x 16B, 8B tail
        float* eb = out + OFF_ENC + (size_t)n0 * 1024;   // 8B-aligned
        if (t == 0) { *(float2*)eb = make_float2(0.f, 0.f); }
        else if (t == 1) { *(float2*)(eb + 131070) = make_float2(0.f, 0.f); }
        float4* ez = (float4*)(eb + 2);
        float4 z = make_float4(0.f, 0.f, 0.f, 0.f);
        for (int i = t; i < 32767; i += 512) ez[i] = z;
    }
    fill_chunk(smem, EN, e4, 0, SM_B0, wid, lane);
    __syncthreads();

    // ---- A fragments straight from XP (fp32 -> f16), kept in regs ----
    // Warp pair (2g, 2g+1) shares row block g; both load the same fragments.
    uint32_t af[8][4];
    {
        int r0 = (wid >> 1) * 16 + (lane >> 2);
        int kc0 = (lane & 3) * 2;
        #pragma unroll
        for (int ks = 0; ks < 8; ks++) {
            int kb = ks * 16 + kc0;
            float2 a = *(const float2*)(XP + r0 * 132 + kb);
            float2 bb = *(const float2*)(XP + (r0 + 8) * 132 + kb);
            float2 c = *(const float2*)(XP + r0 * 132 + kb + 8);
            float2 d = *(const float2*)(XP + (r0 + 8) * 132 + kb + 8);
            __half2 v0 = __floats2half2_rn(a.x, a.y);
            __half2 v1 = __floats2half2_rn(bb.x, bb.y);
            __half2 v2 = __floats2half2_rn(c.x, c.y);
            __half2 v3 = __floats2half2_rn(d.x, d.y);
            af[ks][0] = *(uint32_t*)&v0;  af[ks][1] = *(uint32_t*)&v1;
            af[ks][2] = *(uint32_t*)&v2;  af[ks][3] = *(uint32_t*)&v3;
        }
    }

    // packed-u32 candidate top-4 per owned row over lane's 128-emb subset
    uint32_t A0 = ~0u, A1 = ~0u, A2 = ~0u, A3 = ~0u;   // row r0
    uint32_t B0 = ~0u, B1 = ~0u, B2 = ~0u, B3 = ~0u;   // row r0+8

    const int r_b = lane & 7, seg = lane >> 3;

    // ---- main loop: 16 chunks of 64 embeddings; warp covers its nt half ----
    for (int j = 0; j < 16; j++) {
        __syncthreads();
        const uint32_t bbase = sb + ((j & 1) ? SM_B1 : SM_B0);

        #pragma unroll
        for (int ntp = 0; ntp < 4; ntp++) {
            int nt = h * 4 + ntp;
            uint32_t brow = bbase + (uint32_t)((nt * 8 + r_b) * 256);
            uint32_t bfr[8][2];
            #pragma unroll
            for (int kp = 0; kp < 4; kp++) {
                uint32_t r4[4];
                ldsm4(r4, brow + (uint32_t)(((kp * 4 + seg) ^ r_b) << 4));
                bfr[2 * kp][0] = r4[0]; bfr[2 * kp][1] = r4[1];
                bfr[2 * kp + 1][0] = r4[2]; bfr[2 * kp + 1][1] = r4[3];
            }
            uint32_t c0a = 0, c1a = 0, c0b = 0, c1b = 0;
            mma16816h(c0a, c1a, af[0], bfr[0][0], bfr[0][1]);
            mma16816h(c0b, c1b, af[1], bfr[1][0], bfr[1][1]);
            mma16816h(c0a, c1a, af[2], bfr[2][0], bfr[2][1]);
            mma16816h(c0b, c1b, af[3], bfr[3][0], bfr[3][1]);
            mma16816h(c0a, c1a, af[4], bfr[4][0], bfr[4][1]);
            mma16816h(c0b, c1b, af[5], bfr[5][0], bfr[5][1]);
            mma16816h(c0a, c1a, af[6], bfr[6][0], bfr[6][1]);
            mma16816h(c0b, c1b, af[7], bfr[7][0], bfr[7][1]);
            __half2 r0h = __hadd2(*(__half2*)&c0a, *(__half2*)&c0b);
            __half2 r1h = __hadd2(*(__half2*)&c1a, *(__half2*)&c1b);
            float2 dA = __half22float2(r0h);
            float2 dB = __half22float2(r1h);

            int e = j * 64 + nt * 8 + ((lane & 3) << 1);
            float2 en = *(const float2*)(EN + e);
            ins4u(mpack(fmaf(-2.f, dA.x, en.x), e),     A0, A1, A2, A3);
            ins4u(mpack(fmaf(-2.f, dA.y, en.y), e + 1), A0, A1, A2, A3);
            ins4u(mpack(fmaf(-2.f, dB.x, en.x), e),     B0, B1, B2, B3);
            ins4u(mpack(fmaf(-2.f, dB.y, en.y), e + 1), B0, B1, B2, B3);
        }
        if (j < 15)
            fill_chunk(smem, EN, e4, (j + 1) * 64, ((j & 1) ? SM_B0 : SM_B1), wid, lane);
    }

    // ---- merge lane pairs (subset q with q^2) -> top-4 over 256-emb unions
    // Shuffle SNAPSHOTS of the pre-merge lists (live-register shuffle drops
    // the partner's 2nd..4th elements — the R7/R10 perplexity bug).
    {
        uint32_t s0 = A0, s1 = A1, s2 = A2, s3 = A3, m;
        m = __shfl_xor_sync(0xffffffffu, s0, 2); ins4u(m, A0, A1, A2, A3);
        m = __shfl_xor_sync(0xffffffffu, s1, 2); ins4u(m, A0, A1, A2, A3);
        m = __shfl_xor_sync(0xffffffffu, s2, 2); ins4u(m, A0, A1, A2, A3);
        m = __shfl_xor_sync(0xffffffffu, s3, 2); ins4u(m, A0, A1, A2, A3);
        s0 = B0; s1 = B1; s2 = B2; s3 = B3;
        m = __shfl_xor_sync(0xffffffffu, s0, 2); ins4u(m, B0, B1, B2, B3);
        m = __shfl_xor_sync(0xffffffffu, s1, 2); ins4u(m, B0, B1, B2, B3);
        m = __shfl_xor_sync(0xffffffffu, s2, 2); ins4u(m, B0, B1, B2, B3);
        m = __shfl_xor_sync(0xffffffffu, s3, 2); ins4u(m, B0, B1, B2, B3);
    }
    __syncthreads();   // B buffers dead; pool becomes PK/CI

    // ---- stash 16 candidates per point: warp-half h gives cols h*8..h*8+7
    if ((lane & 3) < 2) {
        int p0 = (wid >> 1) * 16 + (lane >> 2);
        int c0 = h * 8 + (lane & 3) * 4;
        CI[p0 * 16 + c0 + 0] = (int)(A0 & 1023u);
        CI[p0 * 16 + c0 + 1] = (int)(A1 & 1023u);
        CI[p0 * 16 + c0 + 2] = (int)(A2 & 1023u);
        CI[p0 * 16 + c0 + 3] = (int)(A3 & 1023u);
        int p1 = p0 + 8;
        CI[p1 * 16 + c0 + 0] = (int)(B0 & 1023u);
        CI[p1 * 16 + c0 + 1] = (int)(B1 & 1023u);
        CI[p1 * 16 + c0 + 2] = (int)(B2 & 1023u);
        CI[p1 * 16 + c0 + 3] = (int)(B3 & 1023u);
    }
    __syncthreads();

    // ---- exact fp32 rescore: thread = (point, 4 of 16 cands) ----
    {
        int p = t >> 2, c0 = (t & 3) * 4;
        int idx[4]; float acc[4];
        #pragma unroll
        for (int c = 0; c < 4; c++) { idx[c] = CI[p * 16 + c0 + c]; acc[c] = 0.f; }
        #pragma unroll 4
        for (int q = 0; q < 32; q++) {
            float4 xv = *(const float4*)(XP + p * 132 + 4 * q);
            #pragma unroll
            for (int c = 0; c < 4; c++) {
                float4 ev = e4[(size_t)idx[c] * 32 + q];
                acc[c] = fmaf(xv.x, ev.x, fmaf(xv.y, ev.y,
                         fmaf(xv.z, ev.z, fmaf(xv.w, ev.w, acc[c]))));
            }
        }
        #pragma unroll
        for (int c = 0; c < 4; c++)
            PK[p * 16 + c0 + c] = packkey(fmaf(-2.f, acc[c], EN[idx[c]]), idx[c]);
    }
    __syncthreads();

    // ---- exact top-3 per point ----
    if (t < 128) {
        unsigned long long a0 = ~0ULL, a1 = ~0ULL, a2 = ~0ULL;
        #pragma unroll
        for (int c = 0; c < 16; c++) ins3(PK[t * 16 + c], a0, a1, a2);
        SIDX[t * 3 + 0] = (int)(a0 & 0xffffffffu);
        SIDX[t * 3 + 1] = (int)(a1 & 0xffffffffu);
        SIDX[t * 3 + 2] = (int)(a2 & 0xffffffffu);
    }
    __syncthreads();

    // ---- encodings one-hot (3rd nearest) + counts ----
    if (t < 128) {
        int i3 = SIDX[t * 3 + 2];
        out[OFF_ENC + (size_t)(n0 + t) * 1024 + i3] = 1.0f;
        atomicAdd(&g_counts[i3], 1);
    }

    // ---- k=0: topk out + ES half-stage + NCHW + loss, two d-halves ----
    float lsum = 0.f;
    #pragma unroll
    for (int h2 = 0; h2 < 2; h2++) {
        for (int pp = wid; pp < 128; pp += 16) {
            int idx = SIDX[pp * 3];
            const float* er = emb + (size_t)idx * 128 + h2 * 64;
            size_t ob = OFF_TOPK + (size_t)(n0 + pp) * 128 + h2 * 64;
            #pragma unroll
            for (int jj = 0; jj < 2; jj++) {
                int dd = jj * 32 + lane;
                float ev = er[dd];
                float x  = XP[pp * 132 + h2 * 64 + dd];
                out[ob + dd] = x + (ev - x);
                ES[pp * 68 + dd] = ev;
            }
        }
        __syncthreads();
        {
            int p = t & 127, g = t >> 7;   // g 0..3
            size_t qb = OFF_QUANT + (size_t)b * 131072 + (size_t)hw0 + p;
            #pragma unroll 4
            for (int jj = 0; jj < 16; jj++) {
                int dd = g * 16 + jj;
                int d  = h2 * 64 + dd;
                float x  = XP[p * 132 + d];
                float df = ES[p * 68 + dd] - x;
                lsum += df * df;
                out[qb + (size_t)d * 1024] = x + df;
            }
        }
        __syncthreads();
    }
    #pragma unroll
    for (int o = 16; o; o >>= 1) lsum += __shfl_down_sync(0xffffffffu, lsum, o);
    if (lane == 0) atomicAdd(&g_loss_sum, lsum);

    // ---- k=1,2 topk outputs ----
    #pragma unroll
    for (int k = 1; k < 3; k++) {
        for (int pp = wid; pp < 128; pp += 16) {
            int idx = SIDX[pp * 3 + k];
            const float* er = emb + (size_t)idx * 128;
            size_t ob = OFF_TOPK + ((size_t)k * 32768 + (size_t)(n0 + pp)) * 128;
            #pragma unroll
            for (int jj = 0; jj < 4; jj++) {
                int d = jj * 32 + lane;
                float ev = er[d];
                float x  = XP[pp * 132 + d];
                out[ob + d] = x + (ev - x);
            }
        }
    }

    // ---- last-CTA finalize: perplexity + loss, reset counters for next replay
    __threadfence();
    __syncthreads();
    if (t == 0) s_last = (atomicAdd(&g_done, 1) == 255) ? 1 : 0;
    __syncthreads();
    if (s_last && t < 256) {
        float v = 0.f;
        #pragma unroll
        for (int c = 0; c < 4; c++) {
            int i = t * 4 + c;
            float p = (float)(*(volatile int*)&g_counts[i]) * (1.0f / 32768.0f);
            v += p * logf(p + 1e-10f);
            g_counts[i] = 0;
        }
        #pragma unroll
        for (int o = 16; o; o >>= 1) v += __shfl_down_sync(0xffffffffu, v, o);
        if (lane == 0) EN[wid] = v;     // EN smem reused as reduction scratch
        __syncwarp();
        if (t == 0) {
            // wait for all 8 warps' partials via spin-free ordering: they all
            // executed before this point only if t==0 reads after a barrier.
        }
    }
    __syncthreads();
    if (s_last && t == 0) {
        float s = 0.f;
        #pragma unroll
        for (int i = 0; i < 8; i++) s += EN[i];
        out[OFF_PERP] = expf(-s);
        float ls = *(volatile float*)&g_loss_sum;
        out[0] = 0.25f * ls * (1.0f / 4194304.0f);
        g_loss_sum = 0.0f;
        g_done = 0;
    }
}

// ---------------------------------------------------------------------------
extern "C" void kernel_launch(void* const* d_in, const int* in_sizes, int n_in,
                              void* d_out, int out_size) {
    const float* inp = (const float*)d_in[0];   // [32,128,32,32] fp32
    const float* emb = (const float*)d_in[1];   // [1024,128]    fp32
    float* out = (float*)d_out;

    cudaFuncSetAttribute(k_all, cudaFuncAttributeMaxDynamicSharedMemorySize, SMEM_TOTAL);
    k_all<<<256, 512, SMEM_TOTAL>>>(inp, emb, out);
}

// round 17
// speedup vs baseline: 1.5077x; 1.5077x over previous
#include <cuda_runtime.h>
#include <cuda_bf16.h>
#include <cstdint>

// ---------------------------------------------------------------------------
// Output tuple layout (flattened, reference return order)
// ---------------------------------------------------------------------------
static const size_t OFF_QUANT = 1;         // [32,128,32,32]
static const size_t OFF_PERP  = 4194305;   // scalar
static const size_t OFF_ENC   = 4194306;   // [32768,1024]
static const size_t OFF_TOPK  = 37748738;  // [3,32,32,32,128]

__device__ float g_enorm[1024];
__device__ float g_loss_sum;
__device__ int   g_counts[1024];
// bf16 codebook, rows of 256B, pre-swizzled for ldmatrix (16B chunk ^= row&7)
__device__ __align__(16) unsigned char g_embbf[1024 * 256];

// ---------------------------------------------------------------------------
// helpers
// ---------------------------------------------------------------------------
__device__ __forceinline__ uint32_t smem_u32(const void* p) {
    uint32_t a;
    asm("{ .reg .u64 t; cvta.to.shared.u64 t, %1; cvt.u32.u64 %0, t; }" : "=r"(a) : "l"(p));
    return a;
}
// swizzled byte offset within a [row][k] bf16 tile (256B rows, 16B chunks)
__device__ __forceinline__ uint32_t swoff(int row, int k) {
    return (uint32_t)(row * 256 + ((((k >> 3) ^ (row & 7)) << 4)) + (k & 7) * 2);
}

#define CP_ASYNC16(dst, src) asm volatile("cp.async.ca.shared.global [%0], [%1], 16;" :: "r"(dst), "l"(src) : "memory")
#define CP_COMMIT()          asm volatile("cp.async.commit_group;" ::: "memory")
#define CP_WAIT0()           asm volatile("cp.async.wait_group 0;" ::: "memory")

__device__ __forceinline__ void ldsm4(uint32_t r[4], uint32_t addr) {
    asm volatile("ldmatrix.sync.aligned.m8n8.x4.shared.b16 {%0,%1,%2,%3}, [%4];"
                 : "=r"(r[0]), "=r"(r[1]), "=r"(r[2]), "=r"(r[3]) : "r"(addr));
}
__device__ __forceinline__ void mma16816(float& d0, float& d1, float& d2, float& d3,
                                         const uint32_t a[4], uint32_t b0, uint32_t b1) {
    asm volatile("mma.sync.aligned.m16n8k16.row.col.f32.bf16.bf16.f32 "
                 "{%0,%1,%2,%3},{%4,%5,%6,%7},{%8,%9},{%0,%1,%2,%3};"
                 : "+f"(d0), "+f"(d1), "+f"(d2), "+f"(d3)
                 : "r"(a[0]), "r"(a[1]), "r"(a[2]), "r"(a[3]), "r"(b0), "r"(b1));
}

// monotone float->u32, key ROUNDED to 22 bits + 10-bit embedding index
__device__ __forceinline__ uint32_t mpack(float k, int e) {
    uint32_t u = __float_as_uint(k);
    u ^= (uint32_t)((int)u >> 31) | 0x80000000u;
    return ((u + 0x200u) & 0xFFFFFC00u) | (uint32_t)e;
}
// branchless sorted-4 insert (7 IMNMX)
__device__ __forceinline__ void ins4u(uint32_t x, uint32_t& v0, uint32_t& v1,
                                      uint32_t& v2, uint32_t& v3) {
    uint32_t t;
    t = min(v0, x); x = max(v0, x); v0 = t;
    t = min(v1, x); x = max(v1, x); v1 = t;
    t = min(v2, x); x = max(v2, x); v2 = t;
    v3 = min(v3, x);
}

__device__ __forceinline__ unsigned long long packkey(float k, int idx) {
    unsigned u = __float_as_uint(k);
    u = (u & 0x80000000u) ? ~u : (u | 0x80000000u);
    return ((unsigned long long)u << 32) | (unsigned)idx;
}
__device__ __forceinline__ void ins3(unsigned long long pk,
                                     unsigned long long& a0, unsigned long long& a1,
                                     unsigned long long& a2) {
    if (pk < a2) {
        if (pk < a1) { a2 = a1; if (pk < a0) { a1 = a0; a0 = pk; } else a1 = pk; }
        else a2 = pk;
    }
}

// ---------------------------------------------------------------------------
// SMEM layout (bytes).  Pool is a union:
//   main loop : B0 (16KB) | B1 (16KB)   cp.async double buffer
//   rescore   : PK u64[128][8] | CI int[128][8]
//   epilogue  : ES half-tile float[128][68]
// ---------------------------------------------------------------------------
#define SM_XP     0u        // float [128 p][132 d]  (67584B)
#define SM_POOL   67584u
#define SM_B0     (SM_POOL + 0u)
#define SM_B1     (SM_POOL + 16384u)
#define SM_PK     (SM_POOL + 0u)      // u64 [128][8]
#define SM_CI     (SM_POOL + 8192u)   // int [128][8]
#define SM_ES     (SM_POOL + 0u)      // float [128][68]
#define SM_EN     102400u   // float [1024]
#define SM_SIDX   106496u   // int [128][3]
#define SMEM_TOTAL 108032u

// ---------------------------------------------------------------------------
__global__ void k_init(const float* __restrict__ emb) {
    int gtid = blockIdx.x * blockDim.x + threadIdx.x;
    int w = gtid >> 5, lane = gtid & 31;
    if (w < 1024) {
        float4 v = ((const float4*)(emb + (size_t)w * 128))[lane];
        __nv_bfloat162 p0 = __floats2bfloat162_rn(v.x, v.y);
        __nv_bfloat162 p1 = __floats2bfloat162_rn(v.z, v.w);
        *(uint2*)(g_embbf + swoff(w, lane * 4)) =
            make_uint2(*(uint32_t*)&p0, *(uint32_t*)&p1);
        float s = v.x*v.x + v.y*v.y + v.z*v.z + v.w*v.w;
        #pragma unroll
        for (int o = 16; o; o >>= 1) s += __shfl_down_sync(0xffffffffu, s, o);
        if (lane == 0) { g_enorm[w] = s; g_counts[w] = 0; }
    }
    if (gtid == 0) g_loss_sum = 0.0f;
}

// ---------------------------------------------------------------------------
// 384 threads: warps 0..7 = MMA consumers, warps 8..11 = cp.async producers.
// ---------------------------------------------------------------------------
__global__ void __launch_bounds__(384, 2) k_main(const float* __restrict__ inp,
                                                 const float* __restrict__ emb,
                                                 float* __restrict__ out) {
    extern __shared__ char smem[];
    const uint32_t sb = smem_u32(smem);
    float* XP = (float*)(smem + SM_XP);
    float* EN = (float*)(smem + SM_EN);
    int*   CI = (int*)(smem + SM_CI);
    unsigned long long* PK = (unsigned long long*)(smem + SM_PK);
    int*   SIDX = (int*)(smem + SM_SIDX);
    float* ES = (float*)(smem + SM_ES);

    const int t    = threadIdx.x;
    const int lane = t & 31;
    const int wid  = t >> 5;          // 0..11
    const int n0   = blockIdx.x * 128;
    const int b    = n0 >> 10;
    const int hw0  = n0 & 1023;
    const float* inbase = inp + (size_t)b * 131072 + hw0;

    // producers: issue chunk 0 immediately (overlaps prologue)
    if (wid >= 8) {
        uint32_t o = (uint32_t)((t - 256) * 16);
        #pragma unroll
        for (int i = 0; i < 8; i++)
            CP_ASYNC16(sb + SM_B0 + o + (uint32_t)(i * 2048), g_embbf + o + i * 2048);
        CP_COMMIT();
    }

    // ---- prologue: XP fp32, EN, enc zero ----
    for (int i = t; i < 128 * 64; i += 384) {
        int d2 = i >> 7, p = i & 127;
        XP[p * 132 + 2 * d2]     = inbase[(size_t)(2 * d2)     * 1024 + p];
        XP[p * 132 + 2 * d2 + 1] = inbase[(size_t)(2 * d2 + 1) * 1024 + p];
    }
    for (int i = t; i < 1024; i += 384) EN[i] = g_enorm[i];
    {   // zero 128 encoding rows: 8B head, 32766 x 16B, 8B tail
        float* eb = out + OFF_ENC + (size_t)n0 * 1024;   // 8B-aligned
        if (t == 0) { *(float2*)eb = make_float2(0.f, 0.f); }
        else if (t == 1) { *(float2*)(eb + 131070) = make_float2(0.f, 0.f); }
        float4* ez = (float4*)(eb + 2);
        float4 z = make_float4(0.f, 0.f, 0.f, 0.f);
        for (int i = t; i < 32767; i += 384) ez[i] = z;
    }
    __syncthreads();

    // ---- A fragments (consumers only): fp32 XP -> bf16, kept in regs ----
    uint32_t af[8][4];
    if (wid < 8) {
        int r0 = (wid << 4) + (lane >> 2);
        int kc0 = (lane & 3) * 2;
        #pragma unroll
        for (int ks = 0; ks < 8; ks++) {
            int kb = ks * 16 + kc0;
            float2 a = *(const float2*)(XP + r0 * 132 + kb);
            float2 bb = *(const float2*)(XP + (r0 + 8) * 132 + kb);
            float2 c = *(const float2*)(XP + r0 * 132 + kb + 8);
            float2 d = *(const float2*)(XP + (r0 + 8) * 132 + kb + 8);
            __nv_bfloat162 v0 = __floats2bfloat162_rn(a.x, a.y);
            __nv_bfloat162 v1 = __floats2bfloat162_rn(bb.x, bb.y);
            __nv_bfloat162 v2 = __floats2bfloat162_rn(c.x, c.y);
            __nv_bfloat162 v3 = __floats2bfloat162_rn(d.x, d.y);
            af[ks][0] = *(uint32_t*)&v0;  af[ks][1] = *(uint32_t*)&v1;
            af[ks][2] = *(uint32_t*)&v2;  af[ks][3] = *(uint32_t*)&v3;
        }
    }

    // packed-u32 candidate top-4 per owned row, over lane's 256-col subset
    uint32_t A0 = ~0u, A1 = ~0u, A2 = ~0u, A3 = ~0u;   // row r0
    uint32_t B0 = ~0u, B1 = ~0u, B2 = ~0u, B3 = ~0u;   // row r0+8

    const int r_b = lane & 7, seg = lane >> 3;

    // ---- main loop: 16 chunks of 64 embeddings, 1 barrier per chunk ----
    // Producers prefetch chunk j+1 into the opposite buffer while consumers
    // compute chunk j; CP_WAIT0 before the barrier guarantees chunk j landed.
    for (int j = 0; j < 16; j++) {
        if (wid >= 8) CP_WAIT0();
        __syncthreads();
        if (wid < 8) {
            const uint32_t bbase = sb + ((j & 1) ? SM_B1 : SM_B0);
            #pragma unroll
            for (int nt = 0; nt < 8; nt++) {
                uint32_t brow = bbase + (uint32_t)((nt * 8 + r_b) * 256);
                float d0 = 0.f, d1 = 0.f, d2 = 0.f, d3 = 0.f;
                #pragma unroll
                for (int kp = 0; kp < 4; kp++) {
                    uint32_t r4[4];
                    ldsm4(r4, brow + (uint32_t)(((kp * 4 + seg) ^ r_b) << 4));
                    mma16816(d0, d1, d2, d3, af[2 * kp],     r4[0], r4[1]);
                    mma16816(d0, d1, d2, d3, af[2 * kp + 1], r4[2], r4[3]);
                }
                int e = j * 64 + nt * 8 + ((lane & 3) << 1);
                float2 en = *(const float2*)(EN + e);
                ins4u(mpack(fmaf(-2.f, d0, en.x), e),     A0, A1, A2, A3);
                ins4u(mpack(fmaf(-2.f, d1, en.y), e + 1), A0, A1, A2, A3);
                ins4u(mpack(fmaf(-2.f, d2, en.x), e),     B0, B1, B2, B3);
                ins4u(mpack(fmaf(-2.f, d3, en.y), e + 1), B0, B1, B2, B3);
            }
        } else if (j < 15) {
            const unsigned char* src = g_embbf + (size_t)(j + 1) * 16384;
            uint32_t dstb = sb + (((j + 1) & 1) ? SM_B1 : SM_B0);
            uint32_t o = (uint32_t)((t - 256) * 16);
            #pragma unroll
            for (int i = 0; i < 8; i++)
                CP_ASYNC16(dstb + o + (uint32_t)(i * 2048), src + o + i * 2048);
            CP_COMMIT();
        }
    }

    // ---- merge lane pairs (subset s with s^2) -> top-4 over 512-col halves
    // Shuffle SNAPSHOTS of the pre-merge lists (live-register shuffle drops
    // the partner's 2nd..4th elements — the R7/R10 perplexity bug).
    if (wid < 8) {
        uint32_t s0 = A0, s1 = A1, s2 = A2, s3 = A3, m;
        m = __shfl_xor_sync(0xffffffffu, s0, 2); ins4u(m, A0, A1, A2, A3);
        m = __shfl_xor_sync(0xffffffffu, s1, 2); ins4u(m, A0, A1, A2, A3);
        m = __shfl_xor_sync(0xffffffffu, s2, 2); ins4u(m, A0, A1, A2, A3);
        m = __shfl_xor_sync(0xffffffffu, s3, 2); ins4u(m, A0, A1, A2, A3);
        s0 = B0; s1 = B1; s2 = B2; s3 = B3;
        m = __shfl_xor_sync(0xffffffffu, s0, 2); ins4u(m, B0, B1, B2, B3);
        m = __shfl_xor_sync(0xffffffffu, s1, 2); ins4u(m, B0, B1, B2, B3);
        m = __shfl_xor_sync(0xffffffffu, s2, 2); ins4u(m, B0, B1, B2, B3);
        m = __shfl_xor_sync(0xffffffffu, s3, 2); ins4u(m, B0, B1, B2, B3);
    }
    __syncthreads();   // B buffers dead; pool becomes PK/CI

    // ---- stash 8 candidates per point (consumers only; idx = low 10 bits) ----
    if (wid < 8 && (lane & 3) < 2) {
        int p0 = (wid << 4) + (lane >> 2);
        int c0 = (lane & 3) * 4;
        CI[p0 * 8 + c0 + 0] = (int)(A0 & 1023u);
        CI[p0 * 8 + c0 + 1] = (int)(A1 & 1023u);
        CI[p0 * 8 + c0 + 2] = (int)(A2 & 1023u);
        CI[p0 * 8 + c0 + 3] = (int)(A3 & 1023u);
        int p1 = p0 + 8;
        CI[p1 * 8 + c0 + 0] = (int)(B0 & 1023u);
        CI[p1 * 8 + c0 + 1] = (int)(B1 & 1023u);
        CI[p1 * 8 + c0 + 2] = (int)(B2 & 1023u);
        CI[p1 * 8 + c0 + 3] = (int)(B3 & 1023u);
    }
    __syncthreads();

    // ---- exact fp32 rescore: thread = (point, 4 cands), t < 256 ----
    if (t < 256) {
        int p = t >> 1, h2 = t & 1;
        int idx[4]; float acc[4];
        #pragma unroll
        for (int c = 0; c < 4; c++) { idx[c] = CI[p * 8 + h2 * 4 + c]; acc[c] = 0.f; }
        const float4* e4 = (const float4*)emb;
        #pragma unroll 4
        for (int q = 0; q < 32; q++) {
            float4 xv = *(const float4*)(XP + p * 132 + 4 * q);
            #pragma unroll
            for (int c = 0; c < 4; c++) {
                float4 ev = e4[(size_t)idx[c] * 32 + q];
                acc[c] = fmaf(xv.x, ev.x, fmaf(xv.y, ev.y,
                         fmaf(xv.z, ev.z, fmaf(xv.w, ev.w, acc[c]))));
            }
        }
        #pragma unroll
        for (int c = 0; c < 4; c++)
            PK[p * 8 + h2 * 4 + c] = packkey(fmaf(-2.f, acc[c], EN[idx[c]]), idx[c]);
    }
    __syncthreads();

    // ---- exact top-3 per point ----
    if (t < 128) {
        unsigned long long a0 = ~0ULL, a1 = ~0ULL, a2 = ~0ULL;
        #pragma unroll
        for (int c = 0; c < 8; c++) ins3(PK[t * 8 + c], a0, a1, a2);
        SIDX[t * 3 + 0] = (int)(a0 & 0xffffffffu);
        SIDX[t * 3 + 1] = (int)(a1 & 0xffffffffu);
        SIDX[t * 3 + 2] = (int)(a2 & 0xffffffffu);
    }
    __syncthreads();

    // ---- encodings one-hot (3rd nearest) + counts ----
    if (t < 128) {
        int i3 = SIDX[t * 3 + 2];
        out[OFF_ENC + (size_t)(n0 + t) * 1024 + i3] = 1.0f;
        atomicAdd(&g_counts[i3], 1);
    }

    // ---- k=0: topk out + ES half-stage + NCHW + loss, two d-halves ----
    float lsum = 0.f;
    #pragma unroll
    for (int h = 0; h < 2; h++) {
        for (int pp = wid; pp < 128; pp += 12) {
            int idx = SIDX[pp * 3];
            const float* er = emb + (size_t)idx * 128 + h * 64;
            size_t ob = OFF_TOPK + (size_t)(n0 + pp) * 128 + h * 64;
            #pragma unroll
            for (int jj = 0; jj < 2; jj++) {
                int dd = jj * 32 + lane;
                float ev = er[dd];
                float x  = XP[pp * 132 + h * 64 + dd];
                out[ob + dd] = x + (ev - x);
                ES[pp * 68 + dd] = ev;
            }
        }
        __syncthreads();
        if (t < 256) {
            int p = t & 127, g = t >> 7;
            size_t qb = OFF_QUANT + (size_t)b * 131072 + (size_t)hw0 + p;
            #pragma unroll 8
            for (int jj = 0; jj < 32; jj++) {
                int dd = g * 32 + jj;
                int d  = h * 64 + dd;
                float x  = XP[p * 132 + d];
                float df = ES[p * 68 + dd] - x;
                lsum += df * df;
                out[qb + (size_t)d * 1024] = x + df;
            }
        }
        __syncthreads();
    }
    #pragma unroll
    for (int o = 16; o; o >>= 1) lsum += __shfl_down_sync(0xffffffffu, lsum, o);
    if (lane == 0 && wid < 8) atomicAdd(&g_loss_sum, lsum);

    // ---- k=1,2 topk outputs ----
    #pragma unroll
    for (int k = 1; k < 3; k++) {
        for (int pp = wid; pp < 128; pp += 12) {
            int idx = SIDX[pp * 3 + k];
            const float* er = emb + (size_t)idx * 128;
            size_t ob = OFF_TOPK + ((size_t)k * 32768 + (size_t)(n0 + pp)) * 128;
            #pragma unroll
            for (int jj = 0; jj < 4; jj++) {
                int d = jj * 32 + lane;
                float ev = er[d];
                float x  = XP[pp * 132 + d];
                out[ob + d] = x + (ev - x);
            }
        }
    }
}

// ---------------------------------------------------------------------------
__global__ void k_final(float* __restrict__ out) {
    __shared__ float red[32];
    int t = threadIdx.x;  // 1024
    float p = (float)g_counts[t] * (1.0f / 32768.0f);
    float v = p * logf(p + 1e-10f);
    #pragma unroll
    for (int o = 16; o; o >>= 1) v += __shfl_down_sync(0xffffffffu, v, o);
    if ((t & 31) == 0) red[t >> 5] = v;
    __syncthreads();
    if (t < 32) {
        float s = red[t];
        #pragma unroll
        for (int o = 16; o; o >>= 1) s += __shfl_down_sync(0xffffffffu, s, o);
        if (t == 0) {
            out[OFF_PERP] = expf(-s);
            out[0] = 0.25f * g_loss_sum * (1.0f / 4194304.0f);
        }
    }
}

// ---------------------------------------------------------------------------
extern "C" void kernel_launch(void* const* d_in, const int* in_sizes, int n_in,
                              void* d_out, int out_size) {
    const float* inp = (const float*)d_in[0];   // [32,128,32,32] fp32
    const float* emb = (const float*)d_in[1];   // [1024,128]    fp32
    float* out = (float*)d_out;

    cudaFuncSetAttribute(k_main, cudaFuncAttributeMaxDynamicSharedMemorySize, SMEM_TOTAL);

    k_init<<<128, 256>>>(emb);
    k_main<<<256, 384, SMEM_TOTAL>>>(inp, emb, out);
    k_final<<<1, 1024>>>(out);
}